// round 14
// baseline (speedup 1.0000x reference)
#include <cuda_runtime.h>
#include <cuda_bf16.h>
#include <cstdint>
#include <math.h>

#define Bq 4
#define Sq 2048
#define DMq 512
#define Hq 8
#define BSq (Bq * Sq)
#define Y_ELEMS ((size_t)Bq * Sq * DMq)

#define SCALE_L2E 0.18033688011112042f
#define MASK_L2E  (-1.4426950408889634e9f)
#define SHIFT_C   16.0f

// ---------------- Scratch (__device__ globals) ----------------
__device__ __nv_bfloat16 g_iqhi[Bq * Sq * DMq];
__device__ __nv_bfloat16 g_iqlo[Bq * Sq * DMq];
__device__ __nv_bfloat16 g_ikhi[Bq * Sq * DMq];
__device__ __nv_bfloat16 g_iklo[Bq * Sq * DMq];
__device__ __nv_bfloat16 g_ivhi[Bq * Sq * DMq];
__device__ __nv_bfloat16 g_ivlo[Bq * Sq * DMq];
__device__ __nv_bfloat16 g_whi[4][DMq * DMq];
__device__ __nv_bfloat16 g_wlo[4][DMq * DMq];
__device__ __nv_bfloat16 g_qhi[Bq * Sq * DMq];
__device__ __nv_bfloat16 g_qlo[Bq * Sq * DMq];
__device__ __nv_bfloat16 g_khi[Bq * Sq * DMq];
__device__ __nv_bfloat16 g_klo[Bq * Sq * DMq];
__device__ __nv_bfloat16 g_vhi[Bq * Sq * DMq];
__device__ __nv_bfloat16 g_vlo[Bq * Sq * DMq];
__device__ __nv_bfloat16 g_ctxhi[Bq * Sq * DMq];
__device__ __nv_bfloat16 g_ctxlo[Bq * Sq * DMq];

// ---------------- helpers ----------------
__device__ __forceinline__ uint32_t smem_u32(const void* p) {
    uint32_t a;
    asm("{ .reg .u64 t; cvta.to.shared.u64 t, %1; cvt.u32.u64 %0, t; }"
        : "=r"(a) : "l"(p));
    return a;
}

__device__ __forceinline__ void ldsm_x4(uint32_t* r, uint32_t addr) {
    asm volatile("ldmatrix.sync.aligned.m8n8.x4.shared.b16 {%0,%1,%2,%3}, [%4];"
                 : "=r"(r[0]), "=r"(r[1]), "=r"(r[2]), "=r"(r[3]) : "r"(addr));
}

__device__ __forceinline__ void ldsm_x4_trans(uint32_t* r, uint32_t addr) {
    asm volatile("ldmatrix.sync.aligned.m8n8.x4.trans.shared.b16 {%0,%1,%2,%3}, [%4];"
                 : "=r"(r[0]), "=r"(r[1]), "=r"(r[2]), "=r"(r[3]) : "r"(addr));
}

__device__ __forceinline__ void mma_bf16(float* d, const uint32_t* a,
                                         uint32_t b0, uint32_t b1) {
    asm volatile(
        "mma.sync.aligned.m16n8k16.row.col.f32.bf16.bf16.f32 "
        "{%0,%1,%2,%3}, {%4,%5,%6,%7}, {%8,%9}, {%0,%1,%2,%3};"
        : "+f"(d[0]), "+f"(d[1]), "+f"(d[2]), "+f"(d[3])
        : "r"(a[0]), "r"(a[1]), "r"(a[2]), "r"(a[3]), "r"(b0), "r"(b1));
}

__device__ __forceinline__ uint32_t pack_bf16(float x, float y) {
    __nv_bfloat162 t = __floats2bfloat162_rn(x, y);
    return *reinterpret_cast<uint32_t*>(&t);
}

__device__ __forceinline__ void hilo2(float x, float y, uint32_t& hi, uint32_t& lo) {
    __nv_bfloat16 hx = __float2bfloat16_rn(x), hy = __float2bfloat16_rn(y);
    __nv_bfloat162 hv;
    hv.x = hx; hv.y = hy;
    hi = *reinterpret_cast<uint32_t*>(&hv);
    lo = pack_bf16(x - __bfloat162float(hx), y - __bfloat162float(hy));
}

__device__ __forceinline__ void hilo2t(float x, float y, uint32_t& hi, uint32_t& lo) {
    uint32_t ux = __float_as_uint(x), uy = __float_as_uint(y);
    hi = __byte_perm(ux, uy, 0x7632);
    float lx = x - __uint_as_float(ux & 0xFFFF0000u);
    float ly = y - __uint_as_float(uy & 0xFFFF0000u);
    lo = pack_bf16(lx, ly);
}

__device__ __forceinline__ void cp_async16(uint32_t dst, const void* src) {
    asm volatile("cp.async.cg.shared.global [%0], [%1], 16;" :: "r"(dst), "l"(src));
}
#define CP_COMMIT() asm volatile("cp.async.commit_group;" ::: "memory")
#define CP_WAIT1()  asm volatile("cp.async.wait_group 1;" ::: "memory")

// ---------------------------------------------------------------------------
// fp32 -> bf16 hi/lo splits
// ---------------------------------------------------------------------------
__global__ __launch_bounds__(256) void split3_kernel(
    const float* __restrict__ s0, const float* __restrict__ s1,
    const float* __restrict__ s2,
    __nv_bfloat16* __restrict__ h0, __nv_bfloat16* __restrict__ l0,
    __nv_bfloat16* __restrict__ h1, __nv_bfloat16* __restrict__ l1,
    __nv_bfloat16* __restrict__ h2, __nv_bfloat16* __restrict__ l2, int n4)
{
    int z = blockIdx.y;
    const float* src = z == 0 ? s0 : (z == 1 ? s1 : s2);
    __nv_bfloat16* hi = z == 0 ? h0 : (z == 1 ? h1 : h2);
    __nv_bfloat16* lo = z == 0 ? l0 : (z == 1 ? l1 : l2);
    int i = blockIdx.x * 256 + threadIdx.x;
    if (i >= n4) return;
    float4 v = reinterpret_cast<const float4*>(src)[i];
    uint2 h, l;
    hilo2(v.x, v.y, h.x, l.x);
    hilo2(v.z, v.w, h.y, l.y);
    reinterpret_cast<uint2*>(hi)[i] = h;
    reinterpret_cast<uint2*>(lo)[i] = l;
}

__global__ __launch_bounds__(256) void split4_kernel(
    const float* __restrict__ s0, const float* __restrict__ s1,
    const float* __restrict__ s2, const float* __restrict__ s3,
    __nv_bfloat16* __restrict__ hiBase, __nv_bfloat16* __restrict__ loBase, int n4)
{
    int z = blockIdx.y;
    const float* src = z == 0 ? s0 : (z == 1 ? s1 : (z == 2 ? s2 : s3));
    __nv_bfloat16* hi = hiBase + (size_t)z * DMq * DMq;
    __nv_bfloat16* lo = loBase + (size_t)z * DMq * DMq;
    int i = blockIdx.x * 256 + threadIdx.x;
    if (i >= n4) return;
    float4 v = reinterpret_cast<const float4*>(src)[i];
    uint2 h, l;
    hilo2(v.x, v.y, h.x, l.x);
    hilo2(v.z, v.w, h.y, l.y);
    reinterpret_cast<uint2*>(hi)[i] = h;
    reinterpret_cast<uint2*>(lo)[i] = l;
}

// ---------------------------------------------------------------------------
// Pipelined projection GEMM (cp.async 2-stage), bf16x3. (Round-13 proven.)
// ---------------------------------------------------------------------------
#define PJ_STG   71680
#define PJ_AHIo  0
#define PJ_ALOo  18432
#define PJ_WHIo  36864
#define PJ_WLOo  (36864 + 17408)
#define PJ_SMEM_BYTES (2 * PJ_STG)

__device__ __forceinline__ void proj_mma_core(uint32_t stgb, int lane, int wq, int wn,
                                              float acc[2][8][4])
{
    uint32_t ahbase = stgb + PJ_AHIo + (wq * 32) * 144;
    uint32_t albase = stgb + PJ_ALOo + (wq * 32) * 144;
    uint32_t arow = lane & 15;
    uint32_t acolb = (lane >> 4) * 16;
    uint32_t brow = (lane & 7) + ((lane & 8) ? 8 : 0);
    uint32_t bcolb = (lane & 16) ? 16 : 0;
#pragma unroll
    for (int kt = 0; kt < 4; kt++) {
        uint32_t ah0[4], ah1[4], al0[4], al1[4];
        ldsm_x4(ah0, ahbase + arow * 144 + acolb + kt * 32);
        ldsm_x4(ah1, ahbase + (16 + arow) * 144 + acolb + kt * 32);
        ldsm_x4(al0, albase + arow * 144 + acolb + kt * 32);
        ldsm_x4(al1, albase + (16 + arow) * 144 + acolb + kt * 32);
#pragma unroll
        for (int np = 0; np < 4; np++) {
            uint32_t boff = (kt * 16 + brow) * 272 + np * 32 + bcolb + wn * 128;
            uint32_t bb[4];
            ldsm_x4_trans(bb, stgb + PJ_WHIo + boff);
            mma_bf16(acc[0][np * 2 + 0], ah0, bb[0], bb[1]);
            mma_bf16(acc[0][np * 2 + 1], ah0, bb[2], bb[3]);
            mma_bf16(acc[1][np * 2 + 0], ah1, bb[0], bb[1]);
            mma_bf16(acc[1][np * 2 + 1], ah1, bb[2], bb[3]);
            mma_bf16(acc[0][np * 2 + 0], al0, bb[0], bb[1]);
            mma_bf16(acc[0][np * 2 + 1], al0, bb[2], bb[3]);
            mma_bf16(acc[1][np * 2 + 0], al1, bb[0], bb[1]);
            mma_bf16(acc[1][np * 2 + 1], al1, bb[2], bb[3]);
            ldsm_x4_trans(bb, stgb + PJ_WLOo + boff);
            mma_bf16(acc[0][np * 2 + 0], ah0, bb[0], bb[1]);
            mma_bf16(acc[0][np * 2 + 1], ah0, bb[2], bb[3]);
            mma_bf16(acc[1][np * 2 + 0], ah1, bb[0], bb[1]);
            mma_bf16(acc[1][np * 2 + 1], ah1, bb[2], bb[3]);
        }
    }
}

template <bool F32OUT>
__device__ __forceinline__ void proj_pipe_body(
    const __nv_bfloat16* __restrict__ Ahi, const __nv_bfloat16* __restrict__ Alo,
    const __nv_bfloat16* __restrict__ Whi, const __nv_bfloat16* __restrict__ Wlo,
    const float* __restrict__ bias,
    __nv_bfloat16* __restrict__ Ohi, __nv_bfloat16* __restrict__ Olo,
    float* __restrict__ Of, uint32_t sb)
{
    int tid = threadIdx.x;
    int lane = tid & 31, wid = tid >> 5;
    int wq = wid >> 1, wn = wid & 1;
    int m0 = blockIdx.y * 128, n0 = blockIdx.x * 128;

#define PJ_LOAD_STAGE(sidx, kk0) do { \
    uint32_t stb = sb + (sidx) * PJ_STG; \
    _Pragma("unroll") \
    for (int i2 = 0; i2 < 4; i2++) { \
        int i = tid + i2 * 256; \
        int row = i >> 3, ch = i & 7; \
        size_t gg = (size_t)(m0 + row) * DMq + (kk0) + ch * 8; \
        cp_async16(stb + PJ_AHIo + row * 144 + ch * 16, Ahi + gg); \
        cp_async16(stb + PJ_ALOo + row * 144 + ch * 16, Alo + gg); \
    } \
    _Pragma("unroll") \
    for (int i2 = 0; i2 < 4; i2++) { \
        int i = tid + i2 * 256; \
        int row = i >> 4, c8 = i & 15; \
        size_t gg = (size_t)((kk0) + row) * DMq + n0 + c8 * 8; \
        cp_async16(stb + PJ_WHIo + row * 272 + c8 * 16, Whi + gg); \
        cp_async16(stb + PJ_WLOo + row * 272 + c8 * 16, Wlo + gg); \
    } \
} while (0)

    PJ_LOAD_STAGE(0, 0);
    CP_COMMIT();
    PJ_LOAD_STAGE(1, 64);
    CP_COMMIT();

    float acc[2][8][4] = {};

    for (int c = 0; c < 8; c++) {
        CP_WAIT1();
        __syncthreads();
        uint32_t stgb = sb + (uint32_t)(c & 1) * PJ_STG;
        proj_mma_core(stgb, lane, wq, wn, acc);
        __syncthreads();
        if (c + 2 < 8) PJ_LOAD_STAGE(c & 1, (c + 2) * 64);
        CP_COMMIT();
    }

    int g = lane >> 2, tg = lane & 3;
#pragma unroll
    for (int ni = 0; ni < 8; ni++) {
        int col = n0 + wn * 64 + ni * 8 + tg * 2;
        float2 bv2 = *(const float2*)&bias[col];
#pragma unroll
        for (int mi = 0; mi < 2; mi++) {
#pragma unroll
            for (int half = 0; half < 2; half++) {
                int row = m0 + wq * 32 + mi * 16 + g + half * 8;
                float x = acc[mi][ni][half * 2 + 0] + bv2.x;
                float y = acc[mi][ni][half * 2 + 1] + bv2.y;
                size_t idx = (size_t)row * DMq + col;
                if (F32OUT) {
                    *(float2*)&Of[idx] = make_float2(x, y);
                } else {
                    uint32_t hv, lv;
                    hilo2(x, y, hv, lv);
                    *(uint32_t*)&Ohi[idx] = hv;
                    *(uint32_t*)&Olo[idx] = lv;
                }
            }
        }
    }
#undef PJ_LOAD_STAGE
}

__global__ __launch_bounds__(256, 1) void proj3_mma_kernel(
    const __nv_bfloat16* __restrict__ iqhi, const __nv_bfloat16* __restrict__ iqlo,
    const __nv_bfloat16* __restrict__ ikhi, const __nv_bfloat16* __restrict__ iklo,
    const __nv_bfloat16* __restrict__ ivhi, const __nv_bfloat16* __restrict__ ivlo,
    const __nv_bfloat16* __restrict__ whi, const __nv_bfloat16* __restrict__ wlo,
    const float* __restrict__ bq, const float* __restrict__ bk,
    const float* __restrict__ bv,
    __nv_bfloat16* __restrict__ qhi, __nv_bfloat16* __restrict__ qlo,
    __nv_bfloat16* __restrict__ khi, __nv_bfloat16* __restrict__ klo,
    __nv_bfloat16* __restrict__ vhi, __nv_bfloat16* __restrict__ vlo)
{
    extern __shared__ char sm[];
    int z = blockIdx.z;
    const __nv_bfloat16* Ahi = z == 0 ? iqhi : (z == 1 ? ikhi : ivhi);
    const __nv_bfloat16* Alo = z == 0 ? iqlo : (z == 1 ? iklo : ivlo);
    const float* bias = z == 0 ? bq : (z == 1 ? bk : bv);
    __nv_bfloat16* Ohi = z == 0 ? qhi : (z == 1 ? khi : vhi);
    __nv_bfloat16* Olo = z == 0 ? qlo : (z == 1 ? klo : vlo);
    proj_pipe_body<false>(Ahi, Alo, whi + (size_t)z * DMq * DMq,
                          wlo + (size_t)z * DMq * DMq, bias, Ohi, Olo, nullptr,
                          smem_u32(sm));
}

__global__ __launch_bounds__(256, 1) void projo_mma_kernel(
    const __nv_bfloat16* __restrict__ Ahi, const __nv_bfloat16* __restrict__ Alo,
    const __nv_bfloat16* __restrict__ Whi, const __nv_bfloat16* __restrict__ Wlo,
    const float* __restrict__ bias, float* __restrict__ Of)
{
    extern __shared__ char sm[];
    proj_pipe_body<true>(Ahi, Alo, Whi, Wlo, bias, nullptr, nullptr, Of,
                         smem_u32(sm));
}

// ---------------------------------------------------------------------------
// Merged attention, p'-cache, 256 threads/CTA, 16-row warp tiles (occ 25%).
// ---------------------------------------------------------------------------
#define FA_QHIo 0
#define FA_QLOo 18432
#define FA_K0o  36864
#define FA_KSTG 18432
#define FA_V0o  0
#define FA_VSTG 18432
#define FA_A0o  36864
#define FA_ASTG 34816
#define FA_SMEM_BYTES (36864 + 2 * 34816)

// Fused bf16x3 scores for one 64-key chunk, 16 q-rows per warp.
__device__ __forceinline__ void scores_chunk16(
    uint32_t sb, uint32_t kstg, int wid, int lane, float sacc[8][4])
{
    uint32_t ahbase = sb + FA_QHIo + (wid * 16) * 144;
    uint32_t albase = sb + FA_QLOo + (wid * 16) * 144;
    uint32_t arow = lane & 15;
    uint32_t acolb = (lane >> 4) * 16;
    uint32_t brow = (lane & 7) + ((lane & 16) ? 8 : 0);
    uint32_t bcolb = ((lane >> 3) & 1) * 16;
#pragma unroll
    for (int kt = 0; kt < 4; kt++) {
        uint32_t ah[4], al[4];
        ldsm_x4(ah, ahbase + arow * 144 + acolb + kt * 32);
        ldsm_x4(al, albase + arow * 144 + acolb + kt * 32);
#pragma unroll
        for (int np = 0; np < 4; np++) {
            uint32_t boff = (brow + np * 16) * 144 + bcolb + kt * 32;
            uint32_t bb[4];
            ldsm_x4(bb, kstg + boff);
            mma_bf16(sacc[np * 2 + 0], ah, bb[0], bb[1]);
            mma_bf16(sacc[np * 2 + 1], ah, bb[2], bb[3]);
            mma_bf16(sacc[np * 2 + 0], al, bb[0], bb[1]);
            mma_bf16(sacc[np * 2 + 1], al, bb[2], bb[3]);
            ldsm_x4(bb, kstg + 9216 + boff);
            mma_bf16(sacc[np * 2 + 0], ah, bb[0], bb[1]);
            mma_bf16(sacc[np * 2 + 1], ah, bb[2], bb[3]);
        }
    }
}

__global__ __launch_bounds__(256, 2) void attn_merged_kernel(
    const __nv_bfloat16* __restrict__ qhi, const __nv_bfloat16* __restrict__ qlo,
    const __nv_bfloat16* __restrict__ khi, const __nv_bfloat16* __restrict__ klo,
    const __nv_bfloat16* __restrict__ vhi, const __nv_bfloat16* __restrict__ vlo,
    const float* __restrict__ mask,
    float* __restrict__ att,
    __nv_bfloat16* __restrict__ ctxhi, __nv_bfloat16* __restrict__ ctxlo)
{
    extern __shared__ char sm[];
    char* bp = sm;
    uint32_t sb = smem_u32(sm);

    int tid = threadIdx.x;
    int lane = tid & 31, wid = tid >> 5;   // 8 warps, 16 rows each
    int g = lane >> 2, tg = lane & 3;
    int bh = blockIdx.y, b = bh >> 3, h = bh & 7;
    int q0 = blockIdx.x * 128;

    size_t kvbase = (size_t)b * Sq * DMq + h * 64;
    const float* maskrow = mask + (size_t)b * Sq;
    size_t attrow0 = (size_t)bh * Sq + q0;

    // Q tile (pass-1 only)
    for (int it = tid; it < 1024; it += 256) {
        int row = it >> 3, ch = it & 7;
        int so = row * 144 + ch * 16;
        size_t gq = ((size_t)(b * Sq + q0 + row)) * DMq + h * 64 + ch * 8;
        *(uint4*)(bp + FA_QHIo + so) = *(const uint4*)(qhi + gq);
        *(uint4*)(bp + FA_QLOo + so) = *(const uint4*)(qlo + gq);
    }

    const __nv_bfloat16* matsK[2] = {khi, klo};
    const __nv_bfloat16* matsV[2] = {vhi, vlo};

#define LOAD_K_STAGE(sidx, kk0) do { \
    uint32_t stb = sb + FA_K0o + (sidx) * FA_KSTG; \
    _Pragma("unroll") \
    for (int mat = 0; mat < 2; mat++) { \
        const __nv_bfloat16* srcm = matsK[mat]; \
        _Pragma("unroll") \
        for (int i2 = 0; i2 < 2; i2++) { \
            int i = tid + i2 * 256; \
            int row = i >> 3, ch = i & 7; \
            cp_async16(stb + mat * 9216 + row * 144 + ch * 16, \
                       srcm + kvbase + (size_t)((kk0) + row) * DMq + ch * 8); \
        } \
    } \
} while (0)

#define LOAD_VA_STAGE(sidx, kk0) do { \
    uint32_t vstb = sb + FA_V0o + (sidx) * FA_VSTG; \
    _Pragma("unroll") \
    for (int mat = 0; mat < 2; mat++) { \
        const __nv_bfloat16* srcm = matsV[mat]; \
        _Pragma("unroll") \
        for (int i2 = 0; i2 < 2; i2++) { \
            int i = tid + i2 * 256; \
            int row = i >> 3, ch = i & 7; \
            cp_async16(vstb + mat * 9216 + row * 144 + ch * 16, \
                       srcm + kvbase + (size_t)((kk0) + row) * DMq + ch * 8); \
        } \
    } \
    uint32_t astb = sb + FA_A0o + (sidx) * FA_ASTG; \
    _Pragma("unroll") \
    for (int i2 = 0; i2 < 8; i2++) { \
        int i = tid + i2 * 256; \
        int row = i >> 4, ch = i & 15; \
        cp_async16(astb + row * 272 + ch * 16, \
                   att + (attrow0 + row) * Sq + (kk0) + ch * 4); \
    } \
} while (0)

    // ---------------- Pass 1: scores, Z, store unnormalized p' ----------------
    LOAD_K_STAGE(0, 0);
    CP_COMMIT();
    LOAD_K_STAGE(1, 64);
    CP_COMMIT();

    float z0 = 0.f, z1 = 0.f;   // rows wid*16+g, +8

    for (int c = 0; c < 32; c++) {
        CP_WAIT1();
        __syncthreads();
        uint32_t kstg = sb + FA_K0o + (uint32_t)(c & 1) * FA_KSTG;
        int k0 = c * 64;

        float sacc[8][4] = {};
        scores_chunk16(sb, kstg, wid, lane, sacc);

#pragma unroll
        for (int ni = 0; ni < 8; ni++) {
            int col = k0 + ni * 8 + tg * 2;
            float2 mv = *(const float2*)&maskrow[col];
            float mtx = mv.x * MASK_L2E - SHIFT_C, mty = mv.y * MASK_L2E - SHIFT_C;
            float p0 = exp2f(fmaf(sacc[ni][0], SCALE_L2E, mtx));
            float p1 = exp2f(fmaf(sacc[ni][1], SCALE_L2E, mty));
            float p2 = exp2f(fmaf(sacc[ni][2], SCALE_L2E, mtx));
            float p3 = exp2f(fmaf(sacc[ni][3], SCALE_L2E, mty));
            z0 += p0 + p1;
            z1 += p2 + p3;
            int row = wid * 16 + g;
            *(float2*)&att[(attrow0 + row) * Sq + col] = make_float2(p0, p1);
            *(float2*)&att[(attrow0 + row + 8) * Sq + col] = make_float2(p2, p3);
        }
        __syncthreads();
        if (c + 2 < 32) LOAD_K_STAGE(c & 1, (c + 2) * 64);
        CP_COMMIT();
    }

    z0 += __shfl_xor_sync(0xffffffffu, z0, 1);
    z0 += __shfl_xor_sync(0xffffffffu, z0, 2);
    z1 += __shfl_xor_sync(0xffffffffu, z1, 1);
    z1 += __shfl_xor_sync(0xffffffffu, z1, 2);
    float iz0 = 1.0f / z0;
    float iz1 = 1.0f / z1;

    // p' visible to block; smem repurpose barrier.
    __syncthreads();

    // ---------------- Pass 2: p = p'*invZ, att rewrite, ctx += p@V -----------
    LOAD_VA_STAGE(0, 0);
    CP_COMMIT();
    LOAD_VA_STAGE(1, 64);
    CP_COMMIT();

    float cacc[8][4] = {};

    for (int c = 0; c < 32; c++) {
        CP_WAIT1();
        __syncthreads();
        uint32_t vstg = sb + FA_V0o + (uint32_t)(c & 1) * FA_VSTG;
        uint32_t aoff = FA_A0o + (uint32_t)(c & 1) * FA_ASTG;
        int k0 = c * 64;

        float sacc[8][4];
#pragma unroll
        for (int ni = 0; ni < 8; ni++) {
            int colb = (ni * 8 + tg * 2) * 4;
            int col = k0 + ni * 8 + tg * 2;
            int rl = wid * 16 + g;
            float2 a0 = *(const float2*)(bp + aoff + rl * 272 + colb);
            float2 a1 = *(const float2*)(bp + aoff + (rl + 8) * 272 + colb);
            float p0 = a0.x * iz0, p1 = a0.y * iz0;
            float p2 = a1.x * iz1, p3 = a1.y * iz1;
            *(float2*)&att[(attrow0 + rl) * Sq + col] = make_float2(p0, p1);
            *(float2*)&att[(attrow0 + rl + 8) * Sq + col] = make_float2(p2, p3);
            sacc[ni][0] = p0; sacc[ni][1] = p1;
            sacc[ni][2] = p2; sacc[ni][3] = p3;
        }

        {
            uint32_t brow = (lane & 7) + ((lane & 8) ? 8 : 0);
            uint32_t bcolb = (lane & 16) ? 16 : 0;
#pragma unroll
            for (int kt = 0; kt < 4; kt++) {
                int j = kt * 2;
                uint32_t ah[4], al[4];
                hilo2t(sacc[j][0], sacc[j][1], ah[0], al[0]);
                hilo2t(sacc[j][2], sacc[j][3], ah[1], al[1]);
                hilo2t(sacc[j + 1][0], sacc[j + 1][1], ah[2], al[2]);
                hilo2t(sacc[j + 1][2], sacc[j + 1][3], ah[3], al[3]);
#pragma unroll
                for (int np = 0; np < 4; np++) {
                    uint32_t bhv[4], blv[4];
                    ldsm_x4_trans(bhv, vstg + (kt * 16 + brow) * 144 + np * 32 + bcolb);
                    mma_bf16(cacc[np * 2 + 0], ah, bhv[0], bhv[1]);
                    mma_bf16(cacc[np * 2 + 1], ah, bhv[2], bhv[3]);
                    mma_bf16(cacc[np * 2 + 0], al, bhv[0], bhv[1]);
                    mma_bf16(cacc[np * 2 + 1], al, bhv[2], bhv[3]);
                    ldsm_x4_trans(blv, vstg + 9216 + (kt * 16 + brow) * 144 + np * 32 + bcolb);
                    mma_bf16(cacc[np * 2 + 0], ah, blv[0], blv[1]);
                    mma_bf16(cacc[np * 2 + 1], ah, blv[2], blv[3]);
                }
            }
        }
        __syncthreads();
        if (c + 2 < 32) LOAD_VA_STAGE(c & 1, (c + 2) * 64);
        CP_COMMIT();
    }

#pragma unroll
    for (int ni = 0; ni < 8; ni++) {
        int col = h * 64 + ni * 8 + tg * 2;
        int row = q0 + wid * 16 + g;
        uint32_t hv, lv;
        size_t i0 = (size_t)(b * Sq + row) * DMq + col;
        hilo2t(cacc[ni][0], cacc[ni][1], hv, lv);
        *(uint32_t*)&ctxhi[i0] = hv;
        *(uint32_t*)&ctxlo[i0] = lv;
        size_t i1 = (size_t)(b * Sq + row + 8) * DMq + col;
        hilo2t(cacc[ni][2], cacc[ni][3], hv, lv);
        *(uint32_t*)&ctxhi[i1] = hv;
        *(uint32_t*)&ctxlo[i1] = lv;
    }
}

// ---------------------------------------------------------------------------
extern "C" void kernel_launch(void* const* d_in, const int* in_sizes, int n_in,
                              void* d_out, int out_size)
{
    const float* Q    = (const float*)d_in[0];
    const float* K    = (const float*)d_in[1];
    const float* V    = (const float*)d_in[2];
    const float* mask = (const float*)d_in[3];
    const float* Wq   = (const float*)d_in[4];
    const float* bq   = (const float*)d_in[5];
    const float* Wk   = (const float*)d_in[6];
    const float* bk   = (const float*)d_in[7];
    const float* Wv   = (const float*)d_in[8];
    const float* bv   = (const float*)d_in[9];
    const float* Wo   = (const float*)d_in[10];
    const float* bo   = (const float*)d_in[11];

    __nv_bfloat16 *iqhi, *iqlo, *ikhi, *iklo, *ivhi, *ivlo;
    __nv_bfloat16 *whi, *wlo;
    __nv_bfloat16 *qhi, *qlo, *khi, *klo, *vhi, *vlo, *cthi, *ctlo;
    cudaGetSymbolAddress((void**)&iqhi, g_iqhi);
    cudaGetSymbolAddress((void**)&iqlo, g_iqlo);
    cudaGetSymbolAddress((void**)&ikhi, g_ikhi);
    cudaGetSymbolAddress((void**)&iklo, g_iklo);
    cudaGetSymbolAddress((void**)&ivhi, g_ivhi);
    cudaGetSymbolAddress((void**)&ivlo, g_ivlo);
    cudaGetSymbolAddress((void**)&whi, g_whi);
    cudaGetSymbolAddress((void**)&wlo, g_wlo);
    cudaGetSymbolAddress((void**)&qhi, g_qhi);
    cudaGetSymbolAddress((void**)&qlo, g_qlo);
    cudaGetSymbolAddress((void**)&khi, g_khi);
    cudaGetSymbolAddress((void**)&klo, g_klo);
    cudaGetSymbolAddress((void**)&vhi, g_vhi);
    cudaGetSymbolAddress((void**)&vlo, g_vlo);
    cudaGetSymbolAddress((void**)&cthi, g_ctxhi);
    cudaGetSymbolAddress((void**)&ctlo, g_ctxlo);

    float* Y   = (float*)d_out;
    float* att = Y + Y_ELEMS;

    cudaFuncSetAttribute(proj3_mma_kernel,
                         cudaFuncAttributeMaxDynamicSharedMemorySize, PJ_SMEM_BYTES);
    cudaFuncSetAttribute(projo_mma_kernel,
                         cudaFuncAttributeMaxDynamicSharedMemorySize, PJ_SMEM_BYTES);
    cudaFuncSetAttribute(attn_merged_kernel,
                         cudaFuncAttributeMaxDynamicSharedMemorySize, FA_SMEM_BYTES);

    const int NIN4 = (Bq * Sq * DMq) / 4;
    const int NW4  = (DMq * DMq) / 4;

    split3_kernel<<<dim3((NIN4 + 255) / 256, 3), 256>>>(
        Q, K, V, iqhi, iqlo, ikhi, iklo, ivhi, ivlo, NIN4);
    split4_kernel<<<dim3((NW4 + 255) / 256, 4), 256>>>(
        Wq, Wk, Wv, Wo, whi, wlo, NW4);

    dim3 gproj3(DMq / 128, BSq / 128, 3);   // (4, 64, 3)
    proj3_mma_kernel<<<gproj3, 256, PJ_SMEM_BYTES>>>(
        iqhi, iqlo, ikhi, iklo, ivhi, ivlo, whi, wlo, bq, bk, bv,
        qhi, qlo, khi, klo, vhi, vlo);

    dim3 gfa(Sq / 128, Bq * Hq);            // (16, 32)
    attn_merged_kernel<<<gfa, 256, FA_SMEM_BYTES>>>(qhi, qlo, khi, klo, vhi, vlo,
                                                    mask, att, cthi, ctlo);

    dim3 gproj(DMq / 128, BSq / 128);       // (4, 64)
    projo_mma_kernel<<<gproj, 256, PJ_SMEM_BYTES>>>(
        cthi, ctlo, whi + 3 * (size_t)DMq * DMq, wlo + 3 * (size_t)DMq * DMq, bo, Y);
}

// round 15
// speedup vs baseline: 1.0356x; 1.0356x over previous
#include <cuda_runtime.h>
#include <cuda_bf16.h>
#include <cstdint>
#include <math.h>

#define Bq 4
#define Sq 2048
#define DMq 512
#define Hq 8
#define BSq (Bq * Sq)
#define Y_ELEMS ((size_t)Bq * Sq * DMq)

#define SCALE_L2E 0.18033688011112042f
#define MASK_L2E  (-1.4426950408889634e9f)
#define SHIFT_C   16.0f

// ---------------- Scratch (__device__ globals) ----------------
__device__ __nv_bfloat16 g_iqhi[Bq * Sq * DMq];
__device__ __nv_bfloat16 g_iqlo[Bq * Sq * DMq];
__device__ __nv_bfloat16 g_ikhi[Bq * Sq * DMq];
__device__ __nv_bfloat16 g_iklo[Bq * Sq * DMq];
__device__ __nv_bfloat16 g_ivhi[Bq * Sq * DMq];
__device__ __nv_bfloat16 g_ivlo[Bq * Sq * DMq];
__device__ __nv_bfloat16 g_whi[4][DMq * DMq];
__device__ __nv_bfloat16 g_wlo[4][DMq * DMq];
__device__ __nv_bfloat16 g_qhi[Bq * Sq * DMq];
__device__ __nv_bfloat16 g_qlo[Bq * Sq * DMq];
__device__ __nv_bfloat16 g_khi[Bq * Sq * DMq];
__device__ __nv_bfloat16 g_klo[Bq * Sq * DMq];
__device__ __nv_bfloat16 g_vhi[Bq * Sq * DMq];
__device__ __nv_bfloat16 g_vlo[Bq * Sq * DMq];
__device__ __nv_bfloat16 g_ctxhi[Bq * Sq * DMq];
__device__ __nv_bfloat16 g_ctxlo[Bq * Sq * DMq];

// ---------------- helpers ----------------
__device__ __forceinline__ uint32_t smem_u32(const void* p) {
    uint32_t a;
    asm("{ .reg .u64 t; cvta.to.shared.u64 t, %1; cvt.u32.u64 %0, t; }"
        : "=r"(a) : "l"(p));
    return a;
}

__device__ __forceinline__ void ldsm_x4(uint32_t* r, uint32_t addr) {
    asm volatile("ldmatrix.sync.aligned.m8n8.x4.shared.b16 {%0,%1,%2,%3}, [%4];"
                 : "=r"(r[0]), "=r"(r[1]), "=r"(r[2]), "=r"(r[3]) : "r"(addr));
}

__device__ __forceinline__ void ldsm_x4_trans(uint32_t* r, uint32_t addr) {
    asm volatile("ldmatrix.sync.aligned.m8n8.x4.trans.shared.b16 {%0,%1,%2,%3}, [%4];"
                 : "=r"(r[0]), "=r"(r[1]), "=r"(r[2]), "=r"(r[3]) : "r"(addr));
}

__device__ __forceinline__ void mma_bf16(float* d, const uint32_t* a,
                                         uint32_t b0, uint32_t b1) {
    asm volatile(
        "mma.sync.aligned.m16n8k16.row.col.f32.bf16.bf16.f32 "
        "{%0,%1,%2,%3}, {%4,%5,%6,%7}, {%8,%9}, {%0,%1,%2,%3};"
        : "+f"(d[0]), "+f"(d[1]), "+f"(d[2]), "+f"(d[3])
        : "r"(a[0]), "r"(a[1]), "r"(a[2]), "r"(a[3]), "r"(b0), "r"(b1));
}

__device__ __forceinline__ uint32_t pack_bf16(float x, float y) {
    __nv_bfloat162 t = __floats2bfloat162_rn(x, y);
    return *reinterpret_cast<uint32_t*>(&t);
}

__device__ __forceinline__ void hilo2(float x, float y, uint32_t& hi, uint32_t& lo) {
    __nv_bfloat16 hx = __float2bfloat16_rn(x), hy = __float2bfloat16_rn(y);
    __nv_bfloat162 hv;
    hv.x = hx; hv.y = hy;
    hi = *reinterpret_cast<uint32_t*>(&hv);
    lo = pack_bf16(x - __bfloat162float(hx), y - __bfloat162float(hy));
}

__device__ __forceinline__ void hilo2t(float x, float y, uint32_t& hi, uint32_t& lo) {
    uint32_t ux = __float_as_uint(x), uy = __float_as_uint(y);
    hi = __byte_perm(ux, uy, 0x7632);
    float lx = x - __uint_as_float(ux & 0xFFFF0000u);
    float ly = y - __uint_as_float(uy & 0xFFFF0000u);
    lo = pack_bf16(lx, ly);
}

__device__ __forceinline__ void cp_async16(uint32_t dst, const void* src) {
    asm volatile("cp.async.cg.shared.global [%0], [%1], 16;" :: "r"(dst), "l"(src));
}
#define CP_COMMIT() asm volatile("cp.async.commit_group;" ::: "memory")
#define CP_WAIT1()  asm volatile("cp.async.wait_group 1;" ::: "memory")

// ---------------------------------------------------------------------------
// fp32 -> bf16 hi/lo splits
// ---------------------------------------------------------------------------
__global__ __launch_bounds__(256) void split3_kernel(
    const float* __restrict__ s0, const float* __restrict__ s1,
    const float* __restrict__ s2,
    __nv_bfloat16* __restrict__ h0, __nv_bfloat16* __restrict__ l0,
    __nv_bfloat16* __restrict__ h1, __nv_bfloat16* __restrict__ l1,
    __nv_bfloat16* __restrict__ h2, __nv_bfloat16* __restrict__ l2, int n4)
{
    int z = blockIdx.y;
    const float* src = z == 0 ? s0 : (z == 1 ? s1 : s2);
    __nv_bfloat16* hi = z == 0 ? h0 : (z == 1 ? h1 : h2);
    __nv_bfloat16* lo = z == 0 ? l0 : (z == 1 ? l1 : l2);
    int i = blockIdx.x * 256 + threadIdx.x;
    if (i >= n4) return;
    float4 v = reinterpret_cast<const float4*>(src)[i];
    uint2 h, l;
    hilo2(v.x, v.y, h.x, l.x);
    hilo2(v.z, v.w, h.y, l.y);
    reinterpret_cast<uint2*>(hi)[i] = h;
    reinterpret_cast<uint2*>(lo)[i] = l;
}

__global__ __launch_bounds__(256) void split4_kernel(
    const float* __restrict__ s0, const float* __restrict__ s1,
    const float* __restrict__ s2, const float* __restrict__ s3,
    __nv_bfloat16* __restrict__ hiBase, __nv_bfloat16* __restrict__ loBase, int n4)
{
    int z = blockIdx.y;
    const float* src = z == 0 ? s0 : (z == 1 ? s1 : (z == 2 ? s2 : s3));
    __nv_bfloat16* hi = hiBase + (size_t)z * DMq * DMq;
    __nv_bfloat16* lo = loBase + (size_t)z * DMq * DMq;
    int i = blockIdx.x * 256 + threadIdx.x;
    if (i >= n4) return;
    float4 v = reinterpret_cast<const float4*>(src)[i];
    uint2 h, l;
    hilo2(v.x, v.y, h.x, l.x);
    hilo2(v.z, v.w, h.y, l.y);
    reinterpret_cast<uint2*>(hi)[i] = h;
    reinterpret_cast<uint2*>(lo)[i] = l;
}

// ---------------------------------------------------------------------------
// Pipelined projection GEMM (cp.async 2-stage), bf16x3. (Round-13 proven.)
// ---------------------------------------------------------------------------
#define PJ_STG   71680
#define PJ_AHIo  0
#define PJ_ALOo  18432
#define PJ_WHIo  36864
#define PJ_WLOo  (36864 + 17408)
#define PJ_SMEM_BYTES (2 * PJ_STG)

__device__ __forceinline__ void proj_mma_core(uint32_t stgb, int lane, int wq, int wn,
                                              float acc[2][8][4])
{
    uint32_t ahbase = stgb + PJ_AHIo + (wq * 32) * 144;
    uint32_t albase = stgb + PJ_ALOo + (wq * 32) * 144;
    uint32_t arow = lane & 15;
    uint32_t acolb = (lane >> 4) * 16;
    uint32_t brow = (lane & 7) + ((lane & 8) ? 8 : 0);
    uint32_t bcolb = (lane & 16) ? 16 : 0;
#pragma unroll
    for (int kt = 0; kt < 4; kt++) {
        uint32_t ah0[4], ah1[4], al0[4], al1[4];
        ldsm_x4(ah0, ahbase + arow * 144 + acolb + kt * 32);
        ldsm_x4(ah1, ahbase + (16 + arow) * 144 + acolb + kt * 32);
        ldsm_x4(al0, albase + arow * 144 + acolb + kt * 32);
        ldsm_x4(al1, albase + (16 + arow) * 144 + acolb + kt * 32);
#pragma unroll
        for (int np = 0; np < 4; np++) {
            uint32_t boff = (kt * 16 + brow) * 272 + np * 32 + bcolb + wn * 128;
            uint32_t bb[4];
            ldsm_x4_trans(bb, stgb + PJ_WHIo + boff);
            mma_bf16(acc[0][np * 2 + 0], ah0, bb[0], bb[1]);
            mma_bf16(acc[0][np * 2 + 1], ah0, bb[2], bb[3]);
            mma_bf16(acc[1][np * 2 + 0], ah1, bb[0], bb[1]);
            mma_bf16(acc[1][np * 2 + 1], ah1, bb[2], bb[3]);
            mma_bf16(acc[0][np * 2 + 0], al0, bb[0], bb[1]);
            mma_bf16(acc[0][np * 2 + 1], al0, bb[2], bb[3]);
            mma_bf16(acc[1][np * 2 + 0], al1, bb[0], bb[1]);
            mma_bf16(acc[1][np * 2 + 1], al1, bb[2], bb[3]);
            ldsm_x4_trans(bb, stgb + PJ_WLOo + boff);
            mma_bf16(acc[0][np * 2 + 0], ah0, bb[0], bb[1]);
            mma_bf16(acc[0][np * 2 + 1], ah0, bb[2], bb[3]);
            mma_bf16(acc[1][np * 2 + 0], ah1, bb[0], bb[1]);
            mma_bf16(acc[1][np * 2 + 1], ah1, bb[2], bb[3]);
        }
    }
}

template <bool F32OUT>
__device__ __forceinline__ void proj_pipe_body(
    const __nv_bfloat16* __restrict__ Ahi, const __nv_bfloat16* __restrict__ Alo,
    const __nv_bfloat16* __restrict__ Whi, const __nv_bfloat16* __restrict__ Wlo,
    const float* __restrict__ bias,
    __nv_bfloat16* __restrict__ Ohi, __nv_bfloat16* __restrict__ Olo,
    float* __restrict__ Of, uint32_t sb)
{
    int tid = threadIdx.x;
    int lane = tid & 31, wid = tid >> 5;
    int wq = wid >> 1, wn = wid & 1;
    int m0 = blockIdx.y * 128, n0 = blockIdx.x * 128;

#define PJ_LOAD_STAGE(sidx, kk0) do { \
    uint32_t stb = sb + (sidx) * PJ_STG; \
    _Pragma("unroll") \
    for (int i2 = 0; i2 < 4; i2++) { \
        int i = tid + i2 * 256; \
        int row = i >> 3, ch = i & 7; \
        size_t gg = (size_t)(m0 + row) * DMq + (kk0) + ch * 8; \
        cp_async16(stb + PJ_AHIo + row * 144 + ch * 16, Ahi + gg); \
        cp_async16(stb + PJ_ALOo + row * 144 + ch * 16, Alo + gg); \
    } \
    _Pragma("unroll") \
    for (int i2 = 0; i2 < 4; i2++) { \
        int i = tid + i2 * 256; \
        int row = i >> 4, c8 = i & 15; \
        size_t gg = (size_t)((kk0) + row) * DMq + n0 + c8 * 8; \
        cp_async16(stb + PJ_WHIo + row * 272 + c8 * 16, Whi + gg); \
        cp_async16(stb + PJ_WLOo + row * 272 + c8 * 16, Wlo + gg); \
    } \
} while (0)

    PJ_LOAD_STAGE(0, 0);
    CP_COMMIT();
    PJ_LOAD_STAGE(1, 64);
    CP_COMMIT();

    float acc[2][8][4] = {};

    for (int c = 0; c < 8; c++) {
        CP_WAIT1();
        __syncthreads();
        uint32_t stgb = sb + (uint32_t)(c & 1) * PJ_STG;
        proj_mma_core(stgb, lane, wq, wn, acc);
        __syncthreads();
        if (c + 2 < 8) PJ_LOAD_STAGE(c & 1, (c + 2) * 64);
        CP_COMMIT();
    }

    int g = lane >> 2, tg = lane & 3;
#pragma unroll
    for (int ni = 0; ni < 8; ni++) {
        int col = n0 + wn * 64 + ni * 8 + tg * 2;
        float2 bv2 = *(const float2*)&bias[col];
#pragma unroll
        for (int mi = 0; mi < 2; mi++) {
#pragma unroll
            for (int half = 0; half < 2; half++) {
                int row = m0 + wq * 32 + mi * 16 + g + half * 8;
                float x = acc[mi][ni][half * 2 + 0] + bv2.x;
                float y = acc[mi][ni][half * 2 + 1] + bv2.y;
                size_t idx = (size_t)row * DMq + col;
                if (F32OUT) {
                    *(float2*)&Of[idx] = make_float2(x, y);
                } else {
                    uint32_t hv, lv;
                    hilo2(x, y, hv, lv);
                    *(uint32_t*)&Ohi[idx] = hv;
                    *(uint32_t*)&Olo[idx] = lv;
                }
            }
        }
    }
#undef PJ_LOAD_STAGE
}

__global__ __launch_bounds__(256, 1) void proj3_mma_kernel(
    const __nv_bfloat16* __restrict__ iqhi, const __nv_bfloat16* __restrict__ iqlo,
    const __nv_bfloat16* __restrict__ ikhi, const __nv_bfloat16* __restrict__ iklo,
    const __nv_bfloat16* __restrict__ ivhi, const __nv_bfloat16* __restrict__ ivlo,
    const __nv_bfloat16* __restrict__ whi, const __nv_bfloat16* __restrict__ wlo,
    const float* __restrict__ bq, const float* __restrict__ bk,
    const float* __restrict__ bv,
    __nv_bfloat16* __restrict__ qhi, __nv_bfloat16* __restrict__ qlo,
    __nv_bfloat16* __restrict__ khi, __nv_bfloat16* __restrict__ klo,
    __nv_bfloat16* __restrict__ vhi, __nv_bfloat16* __restrict__ vlo)
{
    extern __shared__ char sm[];
    int z = blockIdx.z;
    const __nv_bfloat16* Ahi = z == 0 ? iqhi : (z == 1 ? ikhi : ivhi);
    const __nv_bfloat16* Alo = z == 0 ? iqlo : (z == 1 ? iklo : ivlo);
    const float* bias = z == 0 ? bq : (z == 1 ? bk : bv);
    __nv_bfloat16* Ohi = z == 0 ? qhi : (z == 1 ? khi : vhi);
    __nv_bfloat16* Olo = z == 0 ? qlo : (z == 1 ? klo : vlo);
    proj_pipe_body<false>(Ahi, Alo, whi + (size_t)z * DMq * DMq,
                          wlo + (size_t)z * DMq * DMq, bias, Ohi, Olo, nullptr,
                          smem_u32(sm));
}

__global__ __launch_bounds__(256, 1) void projo_mma_kernel(
    const __nv_bfloat16* __restrict__ Ahi, const __nv_bfloat16* __restrict__ Alo,
    const __nv_bfloat16* __restrict__ Whi, const __nv_bfloat16* __restrict__ Wlo,
    const float* __restrict__ bias, float* __restrict__ Of)
{
    extern __shared__ char sm[];
    proj_pipe_body<true>(Ahi, Alo, Whi, Wlo, bias, nullptr, nullptr, Of,
                         smem_u32(sm));
}

// ---------------------------------------------------------------------------
// Merged attention, p'-cache, 128 threads/CTA, 32-row warp tiles.
// Pass 2 is kt-granular to cut register live range (target 2 CTAs/SM).
// ---------------------------------------------------------------------------
#define FA_QHIo 0
#define FA_QLOo 18432
#define FA_K0o  36864
#define FA_KSTG 18432
#define FA_V0o  0
#define FA_VSTG 18432
#define FA_A0o  36864
#define FA_ASTG 34816
#define FA_SMEM_BYTES (36864 + 2 * 34816)

__device__ __forceinline__ void scores_chunk32(
    uint32_t sb, uint32_t kstg, int wid, int lane, float sacc[2][8][4])
{
    uint32_t ahbase = sb + FA_QHIo + (wid * 32) * 144;
    uint32_t albase = sb + FA_QLOo + (wid * 32) * 144;
    uint32_t arow = lane & 15;
    uint32_t acolb = (lane >> 4) * 16;
    uint32_t brow = (lane & 7) + ((lane & 16) ? 8 : 0);
    uint32_t bcolb = ((lane >> 3) & 1) * 16;
#pragma unroll
    for (int kt = 0; kt < 4; kt++) {
        uint32_t ah0[4], ah1[4], al0[4], al1[4];
        ldsm_x4(ah0, ahbase + arow * 144 + acolb + kt * 32);
        ldsm_x4(ah1, ahbase + (16 + arow) * 144 + acolb + kt * 32);
        ldsm_x4(al0, albase + arow * 144 + acolb + kt * 32);
        ldsm_x4(al1, albase + (16 + arow) * 144 + acolb + kt * 32);
#pragma unroll
        for (int np = 0; np < 4; np++) {
            uint32_t boff = (brow + np * 16) * 144 + bcolb + kt * 32;
            uint32_t bb[4];
            ldsm_x4(bb, kstg + boff);
            mma_bf16(sacc[0][np * 2 + 0], ah0, bb[0], bb[1]);
            mma_bf16(sacc[0][np * 2 + 1], ah0, bb[2], bb[3]);
            mma_bf16(sacc[1][np * 2 + 0], ah1, bb[0], bb[1]);
            mma_bf16(sacc[1][np * 2 + 1], ah1, bb[2], bb[3]);
            mma_bf16(sacc[0][np * 2 + 0], al0, bb[0], bb[1]);
            mma_bf16(sacc[0][np * 2 + 1], al0, bb[2], bb[3]);
            mma_bf16(sacc[1][np * 2 + 0], al1, bb[0], bb[1]);
            mma_bf16(sacc[1][np * 2 + 1], al1, bb[2], bb[3]);
            ldsm_x4(bb, kstg + 9216 + boff);
            mma_bf16(sacc[0][np * 2 + 0], ah0, bb[0], bb[1]);
            mma_bf16(sacc[0][np * 2 + 1], ah0, bb[2], bb[3]);
            mma_bf16(sacc[1][np * 2 + 0], ah1, bb[0], bb[1]);
            mma_bf16(sacc[1][np * 2 + 1], ah1, bb[2], bb[3]);
        }
    }
}

__global__ __launch_bounds__(128, 2) void attn_merged_kernel(
    const __nv_bfloat16* __restrict__ qhi, const __nv_bfloat16* __restrict__ qlo,
    const __nv_bfloat16* __restrict__ khi, const __nv_bfloat16* __restrict__ klo,
    const __nv_bfloat16* __restrict__ vhi, const __nv_bfloat16* __restrict__ vlo,
    const float* __restrict__ mask,
    float* __restrict__ att,
    __nv_bfloat16* __restrict__ ctxhi, __nv_bfloat16* __restrict__ ctxlo)
{
    extern __shared__ char sm[];
    char* bp = sm;
    uint32_t sb = smem_u32(sm);

    int tid = threadIdx.x;
    int lane = tid & 31, wid = tid >> 5;
    int g = lane >> 2, tg = lane & 3;
    int bh = blockIdx.y, b = bh >> 3, h = bh & 7;
    int q0 = blockIdx.x * 128;

    size_t kvbase = (size_t)b * Sq * DMq + h * 64;
    const float* maskrow = mask + (size_t)b * Sq;
    size_t attrow0 = (size_t)bh * Sq + q0;

    for (int it = tid; it < 1024; it += 128) {
        int row = it >> 3, ch = it & 7;
        int so = row * 144 + ch * 16;
        size_t gq = ((size_t)(b * Sq + q0 + row)) * DMq + h * 64 + ch * 8;
        *(uint4*)(bp + FA_QHIo + so) = *(const uint4*)(qhi + gq);
        *(uint4*)(bp + FA_QLOo + so) = *(const uint4*)(qlo + gq);
    }

    const __nv_bfloat16* matsK[2] = {khi, klo};
    const __nv_bfloat16* matsV[2] = {vhi, vlo};

#define LOAD_K_STAGE(sidx, kk0) do { \
    uint32_t stb = sb + FA_K0o + (sidx) * FA_KSTG; \
    _Pragma("unroll") \
    for (int mat = 0; mat < 2; mat++) { \
        const __nv_bfloat16* srcm = matsK[mat]; \
        _Pragma("unroll") \
        for (int i2 = 0; i2 < 4; i2++) { \
            int i = tid + i2 * 128; \
            int row = i >> 3, ch = i & 7; \
            cp_async16(stb + mat * 9216 + row * 144 + ch * 16, \
                       srcm + kvbase + (size_t)((kk0) + row) * DMq + ch * 8); \
        } \
    } \
} while (0)

#define LOAD_VA_STAGE(sidx, kk0) do { \
    uint32_t vstb = sb + FA_V0o + (sidx) * FA_VSTG; \
    _Pragma("unroll") \
    for (int mat = 0; mat < 2; mat++) { \
        const __nv_bfloat16* srcm = matsV[mat]; \
        _Pragma("unroll") \
        for (int i2 = 0; i2 < 4; i2++) { \
            int i = tid + i2 * 128; \
            int row = i >> 3, ch = i & 7; \
            cp_async16(vstb + mat * 9216 + row * 144 + ch * 16, \
                       srcm + kvbase + (size_t)((kk0) + row) * DMq + ch * 8); \
        } \
    } \
    uint32_t astb = sb + FA_A0o + (sidx) * FA_ASTG; \
    _Pragma("unroll") \
    for (int i2 = 0; i2 < 16; i2++) { \
        int i = tid + i2 * 128; \
        int row = i >> 4, ch = i & 15; \
        cp_async16(astb + row * 272 + ch * 16, \
                   att + (attrow0 + row) * Sq + (kk0) + ch * 4); \
    } \
} while (0)

    // ---------------- Pass 1: scores, Z, store unnormalized p' ----------------
    LOAD_K_STAGE(0, 0);
    CP_COMMIT();
    LOAD_K_STAGE(1, 64);
    CP_COMMIT();

    float zz[2][2] = {};

    for (int c = 0; c < 32; c++) {
        CP_WAIT1();
        __syncthreads();
        uint32_t kstg = sb + FA_K0o + (uint32_t)(c & 1) * FA_KSTG;
        int k0 = c * 64;

        float sacc[2][8][4] = {};
        scores_chunk32(sb, kstg, wid, lane, sacc);

#pragma unroll
        for (int ni = 0; ni < 8; ni++) {
            int col = k0 + ni * 8 + tg * 2;
            float2 mv = *(const float2*)&maskrow[col];
            float mtx = mv.x * MASK_L2E - SHIFT_C, mty = mv.y * MASK_L2E - SHIFT_C;
#pragma unroll
            for (int mi = 0; mi < 2; mi++) {
                float p0 = exp2f(fmaf(sacc[mi][ni][0], SCALE_L2E, mtx));
                float p1 = exp2f(fmaf(sacc[mi][ni][1], SCALE_L2E, mty));
                float p2 = exp2f(fmaf(sacc[mi][ni][2], SCALE_L2E, mtx));
                float p3 = exp2f(fmaf(sacc[mi][ni][3], SCALE_L2E, mty));
                zz[mi][0] += p0 + p1;
                zz[mi][1] += p2 + p3;
                int row = wid * 32 + mi * 16 + g;
                *(float2*)&att[(attrow0 + row) * Sq + col] = make_float2(p0, p1);
                *(float2*)&att[(attrow0 + row + 8) * Sq + col] = make_float2(p2, p3);
            }
        }
        __syncthreads();
        if (c + 2 < 32) LOAD_K_STAGE(c & 1, (c + 2) * 64);
        CP_COMMIT();
    }

    float iz[2][2];
#pragma unroll
    for (int mi = 0; mi < 2; mi++)
#pragma unroll
        for (int half = 0; half < 2; half++) {
            float z = zz[mi][half];
            z += __shfl_xor_sync(0xffffffffu, z, 1);
            z += __shfl_xor_sync(0xffffffffu, z, 2);
            iz[mi][half] = 1.0f / z;
        }

    __syncthreads();

    // ---------------- Pass 2 (kt-granular): p = p'*invZ, att, ctx += p@V -----
    LOAD_VA_STAGE(0, 0);
    CP_COMMIT();
    LOAD_VA_STAGE(1, 64);
    CP_COMMIT();

    float cacc[2][8][4] = {};

    for (int c = 0; c < 32; c++) {
        CP_WAIT1();
        __syncthreads();
        uint32_t vstg = sb + FA_V0o + (uint32_t)(c & 1) * FA_VSTG;
        uint32_t aoff = FA_A0o + (uint32_t)(c & 1) * FA_ASTG;
        int k0 = c * 64;

        uint32_t brow = (lane & 7) + ((lane & 8) ? 8 : 0);
        uint32_t bcolb = (lane & 16) ? 16 : 0;

#pragma unroll
        for (int kt = 0; kt < 4; kt++) {
            // Build p A-fragments for this 16-wide k-slice only.
            uint32_t ah[2][4], al[2][4];
#pragma unroll
            for (int jj = 0; jj < 2; jj++) {
                int ni = kt * 2 + jj;
                int colb = (ni * 8 + tg * 2) * 4;
                int col = k0 + ni * 8 + tg * 2;
#pragma unroll
                for (int mi = 0; mi < 2; mi++) {
                    int rl = wid * 32 + mi * 16 + g;
                    float2 a0 = *(const float2*)(bp + aoff + rl * 272 + colb);
                    float2 a1 = *(const float2*)(bp + aoff + (rl + 8) * 272 + colb);
                    float p0 = a0.x * iz[mi][0], p1 = a0.y * iz[mi][0];
                    float p2 = a1.x * iz[mi][1], p3 = a1.y * iz[mi][1];
                    *(float2*)&att[(attrow0 + rl) * Sq + col] = make_float2(p0, p1);
                    *(float2*)&att[(attrow0 + rl + 8) * Sq + col] = make_float2(p2, p3);
                    hilo2t(p0, p1, ah[mi][jj * 2 + 0], al[mi][jj * 2 + 0]);
                    hilo2t(p2, p3, ah[mi][jj * 2 + 1], al[mi][jj * 2 + 1]);
                }
            }
#pragma unroll
            for (int np = 0; np < 4; np++) {
                uint32_t bhv[4], blv[4];
                ldsm_x4_trans(bhv, vstg + (kt * 16 + brow) * 144 + np * 32 + bcolb);
#pragma unroll
                for (int mi = 0; mi < 2; mi++) {
                    mma_bf16(cacc[mi][np * 2 + 0], ah[mi], bhv[0], bhv[1]);
                    mma_bf16(cacc[mi][np * 2 + 1], ah[mi], bhv[2], bhv[3]);
                    mma_bf16(cacc[mi][np * 2 + 0], al[mi], bhv[0], bhv[1]);
                    mma_bf16(cacc[mi][np * 2 + 1], al[mi], bhv[2], bhv[3]);
                }
                ldsm_x4_trans(blv, vstg + 9216 + (kt * 16 + brow) * 144 + np * 32 + bcolb);
#pragma unroll
                for (int mi = 0; mi < 2; mi++) {
                    mma_bf16(cacc[mi][np * 2 + 0], ah[mi], blv[0], blv[1]);
                    mma_bf16(cacc[mi][np * 2 + 1], ah[mi], blv[2], blv[3]);
                }
            }
        }
        __syncthreads();
        if (c + 2 < 32) LOAD_VA_STAGE(c & 1, (c + 2) * 64);
        CP_COMMIT();
    }

#pragma unroll
    for (int mi = 0; mi < 2; mi++) {
#pragma unroll
        for (int ni = 0; ni < 8; ni++) {
            int col = h * 64 + ni * 8 + tg * 2;
            int row = q0 + wid * 32 + mi * 16 + g;
            uint32_t hv, lv;
            size_t i0 = (size_t)(b * Sq + row) * DMq + col;
            hilo2t(cacc[mi][ni][0], cacc[mi][ni][1], hv, lv);
            *(uint32_t*)&ctxhi[i0] = hv;
            *(uint32_t*)&ctxlo[i0] = lv;
            size_t i1 = (size_t)(b * Sq + row + 8) * DMq + col;
            hilo2t(cacc[mi][ni][2], cacc[mi][ni][3], hv, lv);
            *(uint32_t*)&ctxhi[i1] = hv;
            *(uint32_t*)&ctxlo[i1] = lv;
        }
    }
}

// ---------------------------------------------------------------------------
extern "C" void kernel_launch(void* const* d_in, const int* in_sizes, int n_in,
                              void* d_out, int out_size)
{
    const float* Q    = (const float*)d_in[0];
    const float* K    = (const float*)d_in[1];
    const float* V    = (const float*)d_in[2];
    const float* mask = (const float*)d_in[3];
    const float* Wq   = (const float*)d_in[4];
    const float* bq   = (const float*)d_in[5];
    const float* Wk   = (const float*)d_in[6];
    const float* bk   = (const float*)d_in[7];
    const float* Wv   = (const float*)d_in[8];
    const float* bv   = (const float*)d_in[9];
    const float* Wo   = (const float*)d_in[10];
    const float* bo   = (const float*)d_in[11];

    __nv_bfloat16 *iqhi, *iqlo, *ikhi, *iklo, *ivhi, *ivlo;
    __nv_bfloat16 *whi, *wlo;
    __nv_bfloat16 *qhi, *qlo, *khi, *klo, *vhi, *vlo, *cthi, *ctlo;
    cudaGetSymbolAddress((void**)&iqhi, g_iqhi);
    cudaGetSymbolAddress((void**)&iqlo, g_iqlo);
    cudaGetSymbolAddress((void**)&ikhi, g_ikhi);
    cudaGetSymbolAddress((void**)&iklo, g_iklo);
    cudaGetSymbolAddress((void**)&ivhi, g_ivhi);
    cudaGetSymbolAddress((void**)&ivlo, g_ivlo);
    cudaGetSymbolAddress((void**)&whi, g_whi);
    cudaGetSymbolAddress((void**)&wlo, g_wlo);
    cudaGetSymbolAddress((void**)&qhi, g_qhi);
    cudaGetSymbolAddress((void**)&qlo, g_qlo);
    cudaGetSymbolAddress((void**)&khi, g_khi);
    cudaGetSymbolAddress((void**)&klo, g_klo);
    cudaGetSymbolAddress((void**)&vhi, g_vhi);
    cudaGetSymbolAddress((void**)&vlo, g_vlo);
    cudaGetSymbolAddress((void**)&cthi, g_ctxhi);
    cudaGetSymbolAddress((void**)&ctlo, g_ctxlo);

    float* Y   = (float*)d_out;
    float* att = Y + Y_ELEMS;

    cudaFuncSetAttribute(proj3_mma_kernel,
                         cudaFuncAttributeMaxDynamicSharedMemorySize, PJ_SMEM_BYTES);
    cudaFuncSetAttribute(projo_mma_kernel,
                         cudaFuncAttributeMaxDynamicSharedMemorySize, PJ_SMEM_BYTES);
    cudaFuncSetAttribute(attn_merged_kernel,
                         cudaFuncAttributeMaxDynamicSharedMemorySize, FA_SMEM_BYTES);

    const int NIN4 = (Bq * Sq * DMq) / 4;
    const int NW4  = (DMq * DMq) / 4;

    split3_kernel<<<dim3((NIN4 + 255) / 256, 3), 256>>>(
        Q, K, V, iqhi, iqlo, ikhi, iklo, ivhi, ivlo, NIN4);
    split4_kernel<<<dim3((NW4 + 255) / 256, 4), 256>>>(
        Wq, Wk, Wv, Wo, whi, wlo, NW4);

    dim3 gproj3(DMq / 128, BSq / 128, 3);   // (4, 64, 3)
    proj3_mma_kernel<<<gproj3, 256, PJ_SMEM_BYTES>>>(
        iqhi, iqlo, ikhi, iklo, ivhi, ivlo, whi, wlo, bq, bk, bv,
        qhi, qlo, khi, klo, vhi, vlo);

    dim3 gfa(Sq / 128, Bq * Hq);            // (16, 32)
    attn_merged_kernel<<<gfa, 128, FA_SMEM_BYTES>>>(qhi, qlo, khi, klo, vhi, vlo,
                                                    mask, att, cthi, ctlo);

    dim3 gproj(DMq / 128, BSq / 128);       // (4, 64)
    projo_mma_kernel<<<gproj, 256, PJ_SMEM_BYTES>>>(
        cthi, ctlo, whi + 3 * (size_t)DMq * DMq, wlo + 3 * (size_t)DMq * DMq, bo, Y);
}